// round 7
// baseline (speedup 1.0000x reference)
#include <cuda_runtime.h>
#include <cuda_fp16.h>
#include <math.h>
#include <stdint.h>

#define S_   4
#define B_   64
#define K_   3
#define T_   8
#define FPX  96
#define DPX  28
#define CPX  69
#define NPX  4761     // 69*69
#define NPXB 4896     // padded to 9*544 for fp16 tensor path
#define H_   512
#define SB   256      // S_*B_
#define FRPIX 9216    // 96*96

#define ZSPLIT 9
#define KC 32
#define NCH 17        // 544 / 32 chunks per z

typedef unsigned long long ull;

// ---------------- scratch (device globals; no allocation allowed) ----------------
__device__ float g_frame[SB * FRPIX];              // residual frame_left
__device__ __half g_sA[SB * NPXB];                 // scores (fp16), [m][k]
__device__ __half g_W1h[H_ * NPXB];                // W1^T hi (fp16), [n][k]
__device__ __half g_W1l[H_ * NPXB];                // W1^T lo
__device__ float g_hpart[ZSPLIT][SB * H_];         // split-K partials for GEMM1
__device__ float g_h[SB * H_];                     // relu(scores@W1 + b1)
__device__ float g_h2part[4][SB * H_];             // split-K partials for GEMM2
__device__ float g_z[SB * 2];                      // z_where for recon

__device__ __forceinline__ uint32_t smem_u32(const void* p) {
    uint32_t a;
    asm("{ .reg .u64 t; cvta.to.shared.u64 t, %1; cvt.u32.u64 %0, t; }" : "=r"(a) : "l"(p));
    return a;
}

// ---- packed fp32x2 helpers (Blackwell) ----
__device__ __forceinline__ ull f32x2_pack(float lo, float hi) {
    ull p;
    asm("mov.b64 %0, {%1, %2};" : "=l"(p) : "f"(lo), "f"(hi));
    return p;
}
__device__ __forceinline__ ull f32x2_fma(ull a, ull b, ull c) {
    ull d;
    asm("fma.rn.f32x2 %0, %1, %2, %3;" : "=l"(d) : "l"(a), "l"(b), "l"(c));
    return d;
}
__device__ __forceinline__ float f32x2_hsum(ull p) {
    float lo, hi;
    asm("mov.b64 {%0, %1}, %2;" : "=f"(lo), "=f"(hi) : "l"(p));
    return lo + hi;
}

// ---------------- init: frame_left = frames[:, :, timestep] ----------------
__global__ void init_frame_kernel(const float* __restrict__ frames,
                                  const int* __restrict__ ts_p) {
    int idx4 = blockIdx.x * 256 + threadIdx.x;
    if (idx4 >= SB * FRPIX / 4) return;
    int ts = *ts_p;
    int p = idx4 / (FRPIX / 4), off = idx4 % (FRPIX / 4);
    ((float4*)g_frame)[idx4] =
        ((const float4*)frames)[(size_t)(p * T_ + ts) * (FRPIX / 4) + off];
}

// ---------------- once per launch: W1 -> transposed fp16 hi/lo [n][k] ----------------
__global__ void split_W1_kernel(const float* __restrict__ W1) {
    __shared__ float t[32][33];
    int kt = blockIdx.x * 32, nt = blockIdx.y * 32;
    int tx = threadIdx.x, ty = threadIdx.y;   // 32 x 8
    #pragma unroll
    for (int i = 0; i < 32; i += 8) {
        int k = kt + ty + i, n = nt + tx;
        t[ty + i][tx] = (k < NPX) ? W1[(size_t)k * H_ + n] : 0.f;
    }
    __syncthreads();
    #pragma unroll
    for (int i = 0; i < 32; i += 8) {
        int n = nt + ty + i, k = kt + tx;
        float v = t[tx][ty + i];
        __half h = __float2half(v);
        __half l = __float2half(v - __half2float(h));
        g_W1h[(size_t)n * NPXB + k] = h;
        g_W1l[(size_t)n * NPXB + k] = l;
    }
}

// ---------------- fused conv (96x96 (*) 28x28 VALID) via f32x2 + softmax -> fp16 ----
#define SF_STRIDE 97
#define CONV_SMEM_FLOATS (96 * 97 + 40 + 784 + NPX + 32)

__global__ __launch_bounds__(256) void conv_softmax_kernel(
    const float* __restrict__ ck, int k) {
    extern __shared__ float smem[];
    float* sf  = smem;
    float* sk  = sf + 96 * 97 + 40;
    float* ssc = sk + 784;
    float* red = ssc + NPX;

    int p = blockIdx.x;
    int tid = threadIdx.x;

    const float* gf = g_frame + (size_t)p * FRPIX;
    for (int i = tid; i < FRPIX; i += 256) {
        int r = i / FPX, c = i - r * FPX;
        sf[r * SF_STRIDE + c] = gf[i];
    }
    const float* gk = ck + ((size_t)p * K_ + k) * 784;
    for (int i = tid; i < 784; i += 256) sk[i] = gk[i];
    __syncthreads();

    // units: u = cb*69 + r ; 8 outputs per unit via packed f32x2 over kx pairs
    #pragma unroll
    for (int rnd = 0; rnd < 3; rnd++) {
        int u = tid + rnd * 256;
        if (u < 621) {
            int cb = u / 69;
            int r  = u - cb * 69;
            int x0 = cb * 8;
            ull accE[4] = {0ull, 0ull, 0ull, 0ull};   // outputs x0+0,2,4,6
            ull accO[4] = {0ull, 0ull, 0ull, 0ull};   // outputs x0+1,3,5,7
            for (int ky = 0; ky < DPX; ky++) {
                const float* fr = sf + (r + ky) * SF_STRIDE + x0;
                const ull* kp = (const ull*)(sk + ky * DPX);   // 14 kx pairs, 8B aligned
                float w[35];
                #pragma unroll
                for (int i = 0; i < 35; i++) w[i] = fr[i];
                ull pA[17], pB[17];
                #pragma unroll
                for (int i = 0; i < 17; i++) {
                    pA[i] = f32x2_pack(w[2 * i], w[2 * i + 1]);
                    pB[i] = f32x2_pack(w[2 * i + 1], w[2 * i + 2]);
                }
                #pragma unroll
                for (int m = 0; m < 14; m++) {
                    ull k2 = kp[m];
                    #pragma unroll
                    for (int j = 0; j < 4; j++) {
                        accE[j] = f32x2_fma(pA[m + j], k2, accE[j]);
                        accO[j] = f32x2_fma(pB[m + j], k2, accO[j]);
                    }
                }
            }
            int nc = CPX - x0;   // 8 or 5
            #pragma unroll
            for (int j = 0; j < 4; j++) {
                if (2 * j < nc)     ssc[r * CPX + x0 + 2 * j]     = f32x2_hsum(accE[j]);
                if (2 * j + 1 < nc) ssc[r * CPX + x0 + 2 * j + 1] = f32x2_hsum(accO[j]);
            }
        }
    }
    __syncthreads();

    int warp = tid >> 5, lane = tid & 31;
    float lm = -3.4e38f;
    for (int i = tid; i < NPX; i += 256) lm = fmaxf(lm, ssc[i]);
    #pragma unroll
    for (int o = 16; o; o >>= 1) lm = fmaxf(lm, __shfl_xor_sync(0xffffffffu, lm, o));
    if (lane == 0) red[warp] = lm;
    __syncthreads();
    float M = red[0];
    #pragma unroll
    for (int w = 1; w < 8; w++) M = fmaxf(M, red[w]);
    __syncthreads();

    float ls = 0.f;
    for (int i = tid; i < NPX; i += 256) {
        float e = expf(ssc[i] - M);
        ssc[i] = e;
        ls += e;
    }
    #pragma unroll
    for (int o = 16; o; o >>= 1) ls += __shfl_xor_sync(0xffffffffu, ls, o);
    if (lane == 0) red[warp] = ls;
    __syncthreads();
    float tot = 0.f;
    #pragma unroll
    for (int w = 0; w < 8; w++) tot += red[w];
    float inv = 1.f / tot;

    __half* gh = g_sA + (size_t)p * NPXB;
    for (int i = tid; i < NPX; i += 256) gh[i] = __float2half(ssc[i] * inv);
    for (int i = NPX + tid; i < NPXB; i += 256) gh[i] = __float2half(0.f);
}

// ---------------- GEMM1 (mma.sync fp16, 2-term W1 split): scores @ W1^T -------------
// grid (2, 8, ZSPLIT=9) = 144 CTAs (single wave), 256 threads (4x2 warps, 32x32 tiles).
#define ASTB 80                  // bytes per smem row (32 halves + pad)
#define SM_A(b)  ((b) * 20480)
#define SM_BH(b) ((b) * 20480 + 10240)
#define SM_BL(b) ((b) * 20480 + 15360)
#define GEMM1_SMEM_BYTES 40960

#define LDMX4(r0, r1, r2, r3, addr) \
    asm volatile("ldmatrix.sync.aligned.m8n8.x4.shared.b16 {%0,%1,%2,%3}, [%4];" \
                 : "=r"(r0), "=r"(r1), "=r"(r2), "=r"(r3) : "r"(addr))

#define MMA16816F(c, a, b0, b1) \
    asm volatile("mma.sync.aligned.m16n8k16.row.col.f32.f16.f16.f32 " \
                 "{%0,%1,%2,%3}, {%4,%5,%6,%7}, {%8,%9}, {%0,%1,%2,%3};" \
                 : "+f"((c)[0]), "+f"((c)[1]), "+f"((c)[2]), "+f"((c)[3]) \
                 : "r"((a)[0]), "r"((a)[1]), "r"((a)[2]), "r"((a)[3]), \
                   "r"(b0), "r"(b1))

__global__ __launch_bounds__(256) void gemm1_mma_kernel() {
    extern __shared__ char sm[];
    uint32_t sbase = smem_u32(sm);
    int tid = threadIdx.x;
    int wid = tid >> 5, lane = tid & 31;
    int m0 = blockIdx.x * 128, n0 = blockIdx.y * 64;
    int z = blockIdx.z;
    int kbeg0 = z * 544;
    int wm = (wid >> 1) * 32, wn = (wid & 1) * 32;

    auto prefetch = [&](int buf, int kbeg) {
        {   // A: 128 rows x 4 units of 16B -> 512 units, 2 per thread
            uint32_t dst0 = sbase + (uint32_t)SM_A(buf);
            #pragma unroll
            for (int i = 0; i < 2; i++) {
                int u = i * 256 + tid;
                int row = u >> 2, c16 = u & 3;
                const void* g = g_sA + (size_t)(m0 + row) * NPXB + kbeg + c16 * 8;
                uint32_t d = dst0 + (uint32_t)(row * ASTB + c16 * 16);
                asm volatile("cp.async.cg.shared.global [%0], [%1], 16;" :: "r"(d), "l"(g));
            }
        }
        #pragma unroll
        for (int t = 0; t < 2; t++) {   // B hi/lo: 64 rows x 4 units -> 256 units, 1/thread
            const __half* src = t ? g_W1l : g_W1h;
            uint32_t dst0 = sbase + (uint32_t)(t ? SM_BL(buf) : SM_BH(buf));
            int row = tid >> 2, c16 = tid & 3;
            const void* g = src + (size_t)(n0 + row) * NPXB + kbeg + c16 * 8;
            uint32_t d = dst0 + (uint32_t)(row * ASTB + c16 * 16);
            asm volatile("cp.async.cg.shared.global [%0], [%1], 16;" :: "r"(d), "l"(g));
        }
        asm volatile("cp.async.commit_group;");
    };

    float acc[2][4][4] = {};

    prefetch(0, kbeg0);
    asm volatile("cp.async.wait_group 0;");
    __syncthreads();

    for (int ci = 0; ci < NCH; ci++) {
        int buf = ci & 1;
        if (ci + 1 < NCH) prefetch(buf ^ 1, kbeg0 + (ci + 1) * KC);

        uint32_t aA = sbase + (uint32_t)SM_A(buf);
        uint32_t bH = sbase + (uint32_t)SM_BH(buf);
        uint32_t bL = sbase + (uint32_t)SM_BL(buf);

        #pragma unroll
        for (int ks = 0; ks < 2; ks++) {
            int kb = ks * 16;
            uint32_t a[2][4];
            #pragma unroll
            for (int i = 0; i < 2; i++) {
                uint32_t off = (uint32_t)((wm + i * 16 + (lane & 15)) * ASTB
                               + (kb + (lane >> 4) * 8) * 2);
                LDMX4(a[i][0], a[i][1], a[i][2], a[i][3], aA + off);
            }
            uint32_t bh[4][2], bl[4][2];
            #pragma unroll
            for (int jj = 0; jj < 2; jj++) {
                uint32_t off = (uint32_t)((wn + jj * 16 + (lane & 15)) * ASTB
                               + (kb + (lane >> 4) * 8) * 2);
                uint32_t r0, r1, r2, r3;
                LDMX4(r0, r1, r2, r3, bH + off);
                bh[jj * 2][0] = r0; bh[jj * 2][1] = r2;
                bh[jj * 2 + 1][0] = r1; bh[jj * 2 + 1][1] = r3;
                LDMX4(r0, r1, r2, r3, bL + off);
                bl[jj * 2][0] = r0; bl[jj * 2][1] = r2;
                bl[jj * 2 + 1][0] = r1; bl[jj * 2 + 1][1] = r3;
            }
            #pragma unroll
            for (int i = 0; i < 2; i++)
                #pragma unroll
                for (int j = 0; j < 4; j++) {
                    MMA16816F(acc[i][j], a[i], bh[j][0], bh[j][1]);
                    MMA16816F(acc[i][j], a[i], bl[j][0], bl[j][1]);
                }
        }
        if (ci + 1 < NCH) asm volatile("cp.async.wait_group 0;");
        __syncthreads();
    }

    float* outp = g_hpart[z];
    int r = lane >> 2, c2 = (lane & 3) * 2;
    #pragma unroll
    for (int i = 0; i < 2; i++)
        #pragma unroll
        for (int j = 0; j < 4; j++) {
            int mrow = m0 + wm + i * 16 + r;
            int ncol = n0 + wn + j * 8 + c2;
            *(float2*)&outp[(size_t)mrow * H_ + ncol] =
                make_float2(acc[i][j][0], acc[i][j][1]);
            *(float2*)&outp[(size_t)(mrow + 8) * H_ + ncol] =
                make_float2(acc[i][j][2], acc[i][j][3]);
        }
}

// ---------------- reduce split-K partials + bias + relu (float4) ----------------
__global__ void reduce_relu_kernel(const float* __restrict__ b1) {
    int idx4 = blockIdx.x * 256 + threadIdx.x;      // < 32768
    float4 s = ((const float4*)b1)[idx4 & 127];
    #pragma unroll
    for (int r = 0; r < ZSPLIT; r++) {
        float4 v = ((const float4*)g_hpart[r])[idx4];
        s.x += v.x; s.y += v.y; s.z += v.z; s.w += v.w;
    }
    s.x = fmaxf(s.x, 0.f); s.y = fmaxf(s.y, 0.f);
    s.z = fmaxf(s.z, 0.f); s.w = fmaxf(s.w, 0.f);
    ((float4*)g_h)[idx4] = s;
}

// ---------------- GEMM2: h(256x512) @ [Wm1 | Ws1](512x512), splitK=4 ----------------
__global__ __launch_bounds__(256) void gemm2_kernel(
    const float* __restrict__ Wm1, const float* __restrict__ Ws1) {
    __shared__ float As[16][68];
    __shared__ float Bs[16][68];
    int m0 = blockIdx.x * 64, n0 = blockIdx.y * 64;
    int z  = blockIdx.z;
    int kbeg = z * 128;
    const float* Wb = (n0 < 256) ? Wm1 : Ws1;
    int nc0 = n0 & 255;

    int tid = threadIdx.x;
    int tx = tid & 15, ty = tid >> 4;
    int alk = tid & 15, alm = tid >> 4;
    int bln = tid & 63, blk = tid >> 6;

    float acc[4][4] = {};
    for (int kk = 0; kk < 128; kk += 16) {
        #pragma unroll
        for (int i = 0; i < 4; i++) {
            int m = alm + i * 16;
            As[alk][m] = g_h[(size_t)(m0 + m) * H_ + kbeg + kk + alk];
        }
        #pragma unroll
        for (int i = 0; i < 4; i++) {
            int kg = kbeg + kk + blk + i * 4;
            Bs[blk + i * 4][bln] = Wb[(size_t)kg * 256 + nc0 + bln];
        }
        __syncthreads();
        #pragma unroll
        for (int q = 0; q < 16; q++) {
            float a[4], b[4];
            *(float4*)a = *(const float4*)&As[q][ty * 4];
            *(float4*)b = *(const float4*)&Bs[q][tx * 4];
            #pragma unroll
            for (int i = 0; i < 4; i++)
                #pragma unroll
                for (int j = 0; j < 4; j++)
                    acc[i][j] = fmaf(a[i], b[j], acc[i][j]);
        }
        __syncthreads();
    }
    float* outp = g_h2part[z];
    #pragma unroll
    for (int i = 0; i < 4; i++)
        #pragma unroll
        for (int j = 0; j < 4; j++)
            outp[(size_t)(m0 + ty * 4 + i) * H_ + n0 + tx * 4 + j] = acc[i][j];
}

// ---------------- heads ----------------
__global__ void head_kernel(const float* __restrict__ bm1, const float* __restrict__ bs1,
                            const float* __restrict__ Wm2, const float* __restrict__ bm2,
                            const float* __restrict__ Ws2, const float* __restrict__ bs2,
                            const float* __restrict__ eps, float* __restrict__ out, int k) {
    __shared__ float sh[H_];
    __shared__ float sred[8];
    int p = blockIdx.x, tid = threadIdx.x;
    for (int i = tid; i < H_; i += 64) {
        float v = (i < 256) ? bm1[i] : bs1[i - 256];
        #pragma unroll
        for (int z = 0; z < 4; z++) v += g_h2part[z][(size_t)p * H_ + i];
        sh[i] = fmaxf(v, 0.f);
    }
    __syncthreads();

    float pm0 = 0, pm1 = 0, ps0 = 0, ps1 = 0;
    for (int i = tid; i < 256; i += 64) {
        float hm = sh[i], hs = sh[256 + i];
        pm0 = fmaf(hm, Wm2[2 * i],     pm0);
        pm1 = fmaf(hm, Wm2[2 * i + 1], pm1);
        ps0 = fmaf(hs, Ws2[2 * i],     ps0);
        ps1 = fmaf(hs, Ws2[2 * i + 1], ps1);
    }
    #pragma unroll
    for (int o = 16; o; o >>= 1) {
        pm0 += __shfl_down_sync(0xffffffffu, pm0, o);
        pm1 += __shfl_down_sync(0xffffffffu, pm1, o);
        ps0 += __shfl_down_sync(0xffffffffu, ps0, o);
        ps1 += __shfl_down_sync(0xffffffffu, ps1, o);
    }
    int warp = tid >> 5, lane = tid & 31;
    if (lane == 0) {
        sred[warp * 4 + 0] = pm0; sred[warp * 4 + 1] = pm1;
        sred[warp * 4 + 2] = ps0; sred[warp * 4 + 3] = ps1;
    }
    __syncthreads();
    if (tid == 0) {
        float m0 = sred[0] + sred[4], m1 = sred[1] + sred[5];
        float s0 = sred[2] + sred[6], s1 = sred[3] + sred[7];
        float mean0 = tanhf(m0 + bm2[0]), mean1 = tanhf(m1 + bm2[1]);
        float std0  = expf(s0 + bs2[0]),  std1  = expf(s1 + bs2[1]);
        float e0 = eps[(p * K_ + k) * 2], e1 = eps[(p * K_ + k) * 2 + 1];
        float z0 = fmaf(std0, e0, mean0), z1 = fmaf(std1, e1, mean1);
        int o = p * 6 + k * 2;
        out[o] = mean0;        out[o + 1] = mean1;
        out[1536 + o] = std0;  out[1536 + o + 1] = std1;
        out[3072 + o] = z0;    out[3072 + o + 1] = z1;
        g_z[p * 2] = z0; g_z[p * 2 + 1] = z1;
    }
}

// ---------------- recon: bilinear digit placement, subtract from frame_left ----------------
__global__ void recon_kernel(const float* __restrict__ ck, int k) {
    __shared__ float dig[784];
    __shared__ float wx0[96], wx1[96], wy0[96], wy1[96];
    __shared__ int   ix0[96], ix1[96], iy0[96], iy1[96];
    int p = blockIdx.x, tid = threadIdx.x;
    const float* gk = ck + ((size_t)p * K_ + k) * 784;
    for (int i = tid; i < 784; i += 256) dig[i] = gk[i];
    float z0 = g_z[p * 2], z1 = g_z[p * 2 + 1];

    if (tid < 192) {
        int j = tid % 96;
        float zw = (tid < 96) ? z0 : z1;
        const float scale = (float)(96.0 / 28.0);
        float oc = (2.f * j + 1.f) / 96.f - 1.f;
        float pp = ((scale * (oc - zw) + 1.f) * 28.f - 1.f) * 0.5f;
        float p0 = floorf(pp);
        float f  = pp - p0;
        int i0 = (int)p0, i1 = i0 + 1;
        float w0 = (i0 >= 0 && i0 < DPX) ? 1.f - f : 0.f;
        float w1 = (i1 >= 0 && i1 < DPX) ? f : 0.f;
        i0 = min(max(i0, 0), DPX - 1);
        i1 = min(max(i1, 0), DPX - 1);
        if (tid < 96) { wx0[j] = w0; wx1[j] = w1; ix0[j] = i0; ix1[j] = i1; }
        else          { wy0[j] = w0; wy1[j] = w1; iy0[j] = i0; iy1[j] = i1; }
    }
    __syncthreads();

    float* fl = g_frame + (size_t)p * FRPIX;
    for (int idx = tid; idx < FRPIX; idx += 256) {
        int i = idx / 96, j = idx - i * 96;
        float a = wy0[i] * dig[iy0[i] * DPX + ix0[j]] + wy1[i] * dig[iy1[i] * DPX + ix0[j]];
        float b = wy0[i] * dig[iy0[i] * DPX + ix1[j]] + wy1[i] * dig[iy1[i] * DPX + ix1[j]];
        fl[idx] -= (wx0[j] * a + wx1[j] * b);
    }
}

// ---------------- launch ----------------
extern "C" void kernel_launch(void* const* d_in, const int* in_sizes, int n_in,
                              void* d_out, int out_size) {
    const float* frames = (const float*)d_in[0];
    const float* ck     = (const float*)d_in[1];
    const float* eps    = (const float*)d_in[2];
    const float* W1     = (const float*)d_in[3];
    const float* b1     = (const float*)d_in[4];
    const float* Wm1    = (const float*)d_in[5];
    const float* bm1    = (const float*)d_in[6];
    const float* Wm2    = (const float*)d_in[7];
    const float* bm2    = (const float*)d_in[8];
    const float* Ws1    = (const float*)d_in[9];
    const float* bs1    = (const float*)d_in[10];
    const float* Ws2    = (const float*)d_in[11];
    const float* bs2    = (const float*)d_in[12];
    const int*   ts     = (const int*)d_in[13];
    float* out = (float*)d_out;

    const int convSmem = CONV_SMEM_FLOATS * (int)sizeof(float);
    cudaFuncSetAttribute(conv_softmax_kernel,
                         cudaFuncAttributeMaxDynamicSharedMemorySize, convSmem);
    cudaFuncSetAttribute(gemm1_mma_kernel,
                         cudaFuncAttributeMaxDynamicSharedMemorySize, GEMM1_SMEM_BYTES);

    init_frame_kernel<<<(SB * FRPIX / 4 + 255) / 256, 256>>>(frames, ts);
    split_W1_kernel<<<dim3(NPXB / 32, H_ / 32), dim3(32, 8)>>>(W1);

    for (int k = 0; k < K_; k++) {
        conv_softmax_kernel<<<SB, 256, convSmem>>>(ck, k);
        gemm1_mma_kernel<<<dim3(2, 8, ZSPLIT), 256, GEMM1_SMEM_BYTES>>>();
        reduce_relu_kernel<<<128, 256>>>(b1);
        gemm2_kernel<<<dim3(4, 8, 4), 256>>>(Wm1, Ws1);
        head_kernel<<<SB, 64>>>(bm1, bs1, Wm2, bm2, Ws2, bs2, eps, out, k);
        if (k < K_ - 1) recon_kernel<<<SB, 256>>>(ck, k);
    }
}

// round 11
// speedup vs baseline: 1.2632x; 1.2632x over previous
#include <cuda_runtime.h>
#include <cuda_fp16.h>
#include <math.h>
#include <stdint.h>

#define S_   4
#define B_   64
#define K_   3
#define T_   8
#define FPX  96
#define DPX  28
#define CPX  69
#define NPX  4761     // 69*69
#define NPXB 4896     // padded to 9*544 for fp16 tensor path
#define H_   512
#define SB   256      // S_*B_
#define FRPIX 9216    // 96*96

#define ZSPLIT 9
#define KC 32
#define NCH 17        // 544 / 32 chunks per z

// ---------------- scratch (device globals; no allocation allowed) ----------------
__device__ float g_frame[SB * FRPIX];              // residual frame_left
__device__ __half g_sA[SB * NPXB];                 // scores (fp16), [m][k]
__device__ __half g_W1[H_ * NPXB];                 // W1^T (fp16), [n][k]
__device__ float g_hpart[ZSPLIT][SB * H_];         // split-K partials for GEMM1
__device__ float g_h[SB * H_];                     // relu(scores@W1 + b1)
__device__ float g_h2part[4][SB * H_];             // split-K partials for GEMM2
__device__ float g_z[SB * 2];                      // z_where for recon

__device__ __forceinline__ uint32_t smem_u32(const void* p) {
    uint32_t a;
    asm("{ .reg .u64 t; cvta.to.shared.u64 t, %1; cvt.u32.u64 %0, t; }" : "=r"(a) : "l"(p));
    return a;
}

// ---------------- init: frame_left = frames[:, :, timestep] ----------------
__global__ void init_frame_kernel(const float* __restrict__ frames,
                                  const int* __restrict__ ts_p) {
    int idx4 = blockIdx.x * 256 + threadIdx.x;
    if (idx4 >= SB * FRPIX / 4) return;
    int ts = *ts_p;
    int p = idx4 / (FRPIX / 4), off = idx4 % (FRPIX / 4);
    ((float4*)g_frame)[idx4] =
        ((const float4*)frames)[(size_t)(p * T_ + ts) * (FRPIX / 4) + off];
}

// ---------------- once per launch: W1 -> transposed fp16 [n][k] ----------------
__global__ void split_W1_kernel(const float* __restrict__ W1) {
    __shared__ float t[32][33];
    int kt = blockIdx.x * 32, nt = blockIdx.y * 32;
    int tx = threadIdx.x, ty = threadIdx.y;   // 32 x 8
    #pragma unroll
    for (int i = 0; i < 32; i += 8) {
        int k = kt + ty + i, n = nt + tx;
        t[ty + i][tx] = (k < NPX) ? W1[(size_t)k * H_ + n] : 0.f;
    }
    __syncthreads();
    #pragma unroll
    for (int i = 0; i < 32; i += 8) {
        int n = nt + ty + i, k = kt + tx;
        g_W1[(size_t)n * NPXB + k] = __float2half(t[tx][ty + i]);
    }
}

// ---------------- fused conv (VALID 96x96 (*) 28x28 -> 69x69) + softmax -> fp16 ----
#define SF_STRIDE 97
#define CONV_SMEM_FLOATS (96 * 97 + 40 + 784 + NPX + 32)

__global__ __launch_bounds__(256) void conv_softmax_kernel(
    const float* __restrict__ ck, int k) {
    extern __shared__ float smem[];
    float* sf  = smem;
    float* sk  = sf + 96 * 97 + 40;
    float* ssc = sk + 784;
    float* red = ssc + NPX;

    int p = blockIdx.x;
    int tid = threadIdx.x;

    const float* gf = g_frame + (size_t)p * FRPIX;
    for (int i = tid; i < FRPIX; i += 256) {
        int r = i / FPX, c = i - r * FPX;
        sf[r * SF_STRIDE + c] = gf[i];
    }
    const float* gk = ck + ((size_t)p * K_ + k) * 784;
    for (int i = tid; i < 784; i += 256) sk[i] = gk[i];
    __syncthreads();

    #pragma unroll
    for (int rnd = 0; rnd < 3; rnd++) {
        int u = tid + rnd * 256;
        if (u < 621) {
            int cb = u / 69;
            int r  = u - cb * 69;
            int x0 = cb * 8;
            float acc[8] = {0.f,0.f,0.f,0.f,0.f,0.f,0.f,0.f};
            for (int ky = 0; ky < DPX; ky++) {
                const float* fr = sf + (r + ky) * SF_STRIDE + x0;
                const float* kr = sk + ky * DPX;
                float win[35];
                #pragma unroll
                for (int i = 0; i < 35; i++) win[i] = fr[i];
                #pragma unroll
                for (int kx = 0; kx < DPX; kx++) {
                    float kv = kr[kx];
                    #pragma unroll
                    for (int j = 0; j < 8; j++)
                        acc[j] = fmaf(win[kx + j], kv, acc[j]);
                }
            }
            int nc = min(8, CPX - x0);
            for (int j = 0; j < nc; j++) ssc[r * CPX + x0 + j] = acc[j];
        }
    }
    __syncthreads();

    int warp = tid >> 5, lane = tid & 31;
    float lm = -3.4e38f;
    for (int i = tid; i < NPX; i += 256) lm = fmaxf(lm, ssc[i]);
    #pragma unroll
    for (int o = 16; o; o >>= 1) lm = fmaxf(lm, __shfl_xor_sync(0xffffffffu, lm, o));
    if (lane == 0) red[warp] = lm;
    __syncthreads();
    float M = red[0];
    #pragma unroll
    for (int w = 1; w < 8; w++) M = fmaxf(M, red[w]);
    __syncthreads();

    float ls = 0.f;
    for (int i = tid; i < NPX; i += 256) {
        float e = expf(ssc[i] - M);
        ssc[i] = e;
        ls += e;
    }
    #pragma unroll
    for (int o = 16; o; o >>= 1) ls += __shfl_xor_sync(0xffffffffu, ls, o);
    if (lane == 0) red[warp] = ls;
    __syncthreads();
    float tot = 0.f;
    #pragma unroll
    for (int w = 0; w < 8; w++) tot += red[w];
    float inv = 1.f / tot;

    __half* gh = g_sA + (size_t)p * NPXB;
    for (int i = tid; i < NPX; i += 256) gh[i] = __float2half(ssc[i] * inv);
    for (int i = NPX + tid; i < NPXB; i += 256) gh[i] = __float2half(0.f);
}

// ---------------- GEMM1 (mma.sync fp16, single-term): scores @ W1^T -------------
// grid (2, 8, ZSPLIT=9) = 144 CTAs (single wave), 256 threads (4x2 warps, 32x32 tiles).
#define ASTB 80                  // bytes per smem row (32 halves + pad)
#define SM_A(b)  ((b) * 15360)
#define SM_B(b)  ((b) * 15360 + 10240)
#define GEMM1_SMEM_BYTES 30720

#define LDMX4(r0, r1, r2, r3, addr) \
    asm volatile("ldmatrix.sync.aligned.m8n8.x4.shared.b16 {%0,%1,%2,%3}, [%4];" \
                 : "=r"(r0), "=r"(r1), "=r"(r2), "=r"(r3) : "r"(addr))

#define MMA16816F(c, a, b0, b1) \
    asm volatile("mma.sync.aligned.m16n8k16.row.col.f32.f16.f16.f32 " \
                 "{%0,%1,%2,%3}, {%4,%5,%6,%7}, {%8,%9}, {%0,%1,%2,%3};" \
                 : "+f"((c)[0]), "+f"((c)[1]), "+f"((c)[2]), "+f"((c)[3]) \
                 : "r"((a)[0]), "r"((a)[1]), "r"((a)[2]), "r"((a)[3]), \
                   "r"(b0), "r"(b1))

__global__ __launch_bounds__(256) void gemm1_mma_kernel() {
    extern __shared__ char sm[];
    uint32_t sbase = smem_u32(sm);
    int tid = threadIdx.x;
    int wid = tid >> 5, lane = tid & 31;
    int m0 = blockIdx.x * 128, n0 = blockIdx.y * 64;
    int z = blockIdx.z;
    int kbeg0 = z * 544;
    int wm = (wid >> 1) * 32, wn = (wid & 1) * 32;

    auto prefetch = [&](int buf, int kbeg) {
        {   // A: 128 rows x 4 units of 16B -> 512 units, 2 per thread
            uint32_t dst0 = sbase + (uint32_t)SM_A(buf);
            #pragma unroll
            for (int i = 0; i < 2; i++) {
                int u = i * 256 + tid;
                int row = u >> 2, c16 = u & 3;
                const void* g = g_sA + (size_t)(m0 + row) * NPXB + kbeg + c16 * 8;
                uint32_t d = dst0 + (uint32_t)(row * ASTB + c16 * 16);
                asm volatile("cp.async.cg.shared.global [%0], [%1], 16;" :: "r"(d), "l"(g));
            }
        }
        {   // B: 64 rows x 4 units -> 256 units, 1 per thread
            uint32_t dst0 = sbase + (uint32_t)SM_B(buf);
            int row = tid >> 2, c16 = tid & 3;
            const void* g = g_W1 + (size_t)(n0 + row) * NPXB + kbeg + c16 * 8;
            uint32_t d = dst0 + (uint32_t)(row * ASTB + c16 * 16);
            asm volatile("cp.async.cg.shared.global [%0], [%1], 16;" :: "r"(d), "l"(g));
        }
        asm volatile("cp.async.commit_group;");
    };

    float acc[2][4][4] = {};

    prefetch(0, kbeg0);
    asm volatile("cp.async.wait_group 0;");
    __syncthreads();

    for (int ci = 0; ci < NCH; ci++) {
        int buf = ci & 1;
        if (ci + 1 < NCH) prefetch(buf ^ 1, kbeg0 + (ci + 1) * KC);

        uint32_t aA = sbase + (uint32_t)SM_A(buf);
        uint32_t bB = sbase + (uint32_t)SM_B(buf);

        #pragma unroll
        for (int ks = 0; ks < 2; ks++) {
            int kb = ks * 16;
            uint32_t a[2][4];
            #pragma unroll
            for (int i = 0; i < 2; i++) {
                uint32_t off = (uint32_t)((wm + i * 16 + (lane & 15)) * ASTB
                               + (kb + (lane >> 4) * 8) * 2);
                LDMX4(a[i][0], a[i][1], a[i][2], a[i][3], aA + off);
            }
            uint32_t bh[4][2];
            #pragma unroll
            for (int jj = 0; jj < 2; jj++) {
                uint32_t off = (uint32_t)((wn + jj * 16 + (lane & 15)) * ASTB
                               + (kb + (lane >> 4) * 8) * 2);
                uint32_t r0, r1, r2, r3;
                LDMX4(r0, r1, r2, r3, bB + off);
                bh[jj * 2][0] = r0; bh[jj * 2][1] = r2;
                bh[jj * 2 + 1][0] = r1; bh[jj * 2 + 1][1] = r3;
            }
            #pragma unroll
            for (int i = 0; i < 2; i++)
                #pragma unroll
                for (int j = 0; j < 4; j++)
                    MMA16816F(acc[i][j], a[i], bh[j][0], bh[j][1]);
        }
        if (ci + 1 < NCH) asm volatile("cp.async.wait_group 0;");
        __syncthreads();
    }

    float* outp = g_hpart[z];
    int r = lane >> 2, c2 = (lane & 3) * 2;
    #pragma unroll
    for (int i = 0; i < 2; i++)
        #pragma unroll
        for (int j = 0; j < 4; j++) {
            int mrow = m0 + wm + i * 16 + r;
            int ncol = n0 + wn + j * 8 + c2;
            *(float2*)&outp[(size_t)mrow * H_ + ncol] =
                make_float2(acc[i][j][0], acc[i][j][1]);
            *(float2*)&outp[(size_t)(mrow + 8) * H_ + ncol] =
                make_float2(acc[i][j][2], acc[i][j][3]);
        }
}

// ---------------- reduce split-K partials + bias + relu (float4) ----------------
__global__ void reduce_relu_kernel(const float* __restrict__ b1) {
    int idx4 = blockIdx.x * 256 + threadIdx.x;      // < 32768
    float4 s = ((const float4*)b1)[idx4 & 127];
    #pragma unroll
    for (int r = 0; r < ZSPLIT; r++) {
        float4 v = ((const float4*)g_hpart[r])[idx4];
        s.x += v.x; s.y += v.y; s.z += v.z; s.w += v.w;
    }
    s.x = fmaxf(s.x, 0.f); s.y = fmaxf(s.y, 0.f);
    s.z = fmaxf(s.z, 0.f); s.w = fmaxf(s.w, 0.f);
    ((float4*)g_h)[idx4] = s;
}

// ---------------- GEMM2: h(256x512) @ [Wm1 | Ws1](512x512), splitK=4 ----------------
__global__ __launch_bounds__(256) void gemm2_kernel(
    const float* __restrict__ Wm1, const float* __restrict__ Ws1) {
    __shared__ float As[16][68];
    __shared__ float Bs[16][68];
    int m0 = blockIdx.x * 64, n0 = blockIdx.y * 64;
    int z  = blockIdx.z;
    int kbeg = z * 128;
    const float* Wb = (n0 < 256) ? Wm1 : Ws1;
    int nc0 = n0 & 255;

    int tid = threadIdx.x;
    int tx = tid & 15, ty = tid >> 4;
    int alk = tid & 15, alm = tid >> 4;
    int bln = tid & 63, blk = tid >> 6;

    float acc[4][4] = {};
    for (int kk = 0; kk < 128; kk += 16) {
        #pragma unroll
        for (int i = 0; i < 4; i++) {
            int m = alm + i * 16;
            As[alk][m] = g_h[(size_t)(m0 + m) * H_ + kbeg + kk + alk];
        }
        #pragma unroll
        for (int i = 0; i < 4; i++) {
            int kg = kbeg + kk + blk + i * 4;
            Bs[blk + i * 4][bln] = Wb[(size_t)kg * 256 + nc0 + bln];
        }
        __syncthreads();
        #pragma unroll
        for (int q = 0; q < 16; q++) {
            float a[4], b[4];
            *(float4*)a = *(const float4*)&As[q][ty * 4];
            *(float4*)b = *(const float4*)&Bs[q][tx * 4];
            #pragma unroll
            for (int i = 0; i < 4; i++)
                #pragma unroll
                for (int j = 0; j < 4; j++)
                    acc[i][j] = fmaf(a[i], b[j], acc[i][j]);
        }
        __syncthreads();
    }
    float* outp = g_h2part[z];
    #pragma unroll
    for (int i = 0; i < 4; i++)
        #pragma unroll
        for (int j = 0; j < 4; j++)
            outp[(size_t)(m0 + ty * 4 + i) * H_ + n0 + tx * 4 + j] = acc[i][j];
}

// ---------------- heads ----------------
__global__ void head_kernel(const float* __restrict__ bm1, const float* __restrict__ bs1,
                            const float* __restrict__ Wm2, const float* __restrict__ bm2,
                            const float* __restrict__ Ws2, const float* __restrict__ bs2,
                            const float* __restrict__ eps, float* __restrict__ out, int k) {
    __shared__ float sh[H_];
    __shared__ float sred[8];
    int p = blockIdx.x, tid = threadIdx.x;
    for (int i = tid; i < H_; i += 64) {
        float v = (i < 256) ? bm1[i] : bs1[i - 256];
        #pragma unroll
        for (int z = 0; z < 4; z++) v += g_h2part[z][(size_t)p * H_ + i];
        sh[i] = fmaxf(v, 0.f);
    }
    __syncthreads();

    float pm0 = 0, pm1 = 0, ps0 = 0, ps1 = 0;
    for (int i = tid; i < 256; i += 64) {
        float hm = sh[i], hs = sh[256 + i];
        pm0 = fmaf(hm, Wm2[2 * i],     pm0);
        pm1 = fmaf(hm, Wm2[2 * i + 1], pm1);
        ps0 = fmaf(hs, Ws2[2 * i],     ps0);
        ps1 = fmaf(hs, Ws2[2 * i + 1], ps1);
    }
    #pragma unroll
    for (int o = 16; o; o >>= 1) {
        pm0 += __shfl_down_sync(0xffffffffu, pm0, o);
        pm1 += __shfl_down_sync(0xffffffffu, pm1, o);
        ps0 += __shfl_down_sync(0xffffffffu, ps0, o);
        ps1 += __shfl_down_sync(0xffffffffu, ps1, o);
    }
    int warp = tid >> 5, lane = tid & 31;
    if (lane == 0) {
        sred[warp * 4 + 0] = pm0; sred[warp * 4 + 1] = pm1;
        sred[warp * 4 + 2] = ps0; sred[warp * 4 + 3] = ps1;
    }
    __syncthreads();
    if (tid == 0) {
        float m0 = sred[0] + sred[4], m1 = sred[1] + sred[5];
        float s0 = sred[2] + sred[6], s1 = sred[3] + sred[7];
        float mean0 = tanhf(m0 + bm2[0]), mean1 = tanhf(m1 + bm2[1]);
        float std0  = expf(s0 + bs2[0]),  std1  = expf(s1 + bs2[1]);
        float e0 = eps[(p * K_ + k) * 2], e1 = eps[(p * K_ + k) * 2 + 1];
        float z0 = fmaf(std0, e0, mean0), z1 = fmaf(std1, e1, mean1);
        int o = p * 6 + k * 2;
        out[o] = mean0;        out[o + 1] = mean1;
        out[1536 + o] = std0;  out[1536 + o + 1] = std1;
        out[3072 + o] = z0;    out[3072 + o + 1] = z1;
        g_z[p * 2] = z0; g_z[p * 2 + 1] = z1;
    }
}

// ---------------- recon: bilinear digit placement, subtract from frame_left ----------------
__global__ void recon_kernel(const float* __restrict__ ck, int k) {
    __shared__ float dig[784];
    __shared__ float wx0[96], wx1[96], wy0[96], wy1[96];
    __shared__ int   ix0[96], ix1[96], iy0[96], iy1[96];
    int p = blockIdx.x, tid = threadIdx.x;
    const float* gk = ck + ((size_t)p * K_ + k) * 784;
    for (int i = tid; i < 784; i += 256) dig[i] = gk[i];
    float z0 = g_z[p * 2], z1 = g_z[p * 2 + 1];

    if (tid < 192) {
        int j = tid % 96;
        float zw = (tid < 96) ? z0 : z1;
        const float scale = (float)(96.0 / 28.0);
        float oc = (2.f * j + 1.f) / 96.f - 1.f;
        float pp = ((scale * (oc - zw) + 1.f) * 28.f - 1.f) * 0.5f;
        float p0 = floorf(pp);
        float f  = pp - p0;
        int i0 = (int)p0, i1 = i0 + 1;
        float w0 = (i0 >= 0 && i0 < DPX) ? 1.f - f : 0.f;
        float w1 = (i1 >= 0 && i1 < DPX) ? f : 0.f;
        i0 = min(max(i0, 0), DPX - 1);
        i1 = min(max(i1, 0), DPX - 1);
        if (tid < 96) { wx0[j] = w0; wx1[j] = w1; ix0[j] = i0; ix1[j] = i1; }
        else          { wy0[j] = w0; wy1[j] = w1; iy0[j] = i0; iy1[j] = i1; }
    }
    __syncthreads();

    float* fl = g_frame + (size_t)p * FRPIX;
    for (int idx = tid; idx < FRPIX; idx += 256) {
        int i = idx / 96, j = idx - i * 96;
        float a = wy0[i] * dig[iy0[i] * DPX + ix0[j]] + wy1[i] * dig[iy1[i] * DPX + ix0[j]];
        float b = wy0[i] * dig[iy0[i] * DPX + ix1[j]] + wy1[i] * dig[iy1[i] * DPX + ix1[j]];
        fl[idx] -= (wx0[j] * a + wx1[j] * b);
    }
}

// ---------------- launch ----------------
extern "C" void kernel_launch(void* const* d_in, const int* in_sizes, int n_in,
                              void* d_out, int out_size) {
    const float* frames = (const float*)d_in[0];
    const float* ck     = (const float*)d_in[1];
    const float* eps    = (const float*)d_in[2];
    const float* W1     = (const float*)d_in[3];
    const float* b1     = (const float*)d_in[4];
    const float* Wm1    = (const float*)d_in[5];
    const float* bm1    = (const float*)d_in[6];
    const float* Wm2    = (const float*)d_in[7];
    const float* bm2    = (const float*)d_in[8];
    const float* Ws1    = (const float*)d_in[9];
    const float* bs1    = (const float*)d_in[10];
    const float* Ws2    = (const float*)d_in[11];
    const float* bs2    = (const float*)d_in[12];
    const int*   ts     = (const int*)d_in[13];
    float* out = (float*)d_out;

    const int convSmem = CONV_SMEM_FLOATS * (int)sizeof(float);
    cudaFuncSetAttribute(conv_softmax_kernel,
                         cudaFuncAttributeMaxDynamicSharedMemorySize, convSmem);
    cudaFuncSetAttribute(gemm1_mma_kernel,
                         cudaFuncAttributeMaxDynamicSharedMemorySize, GEMM1_SMEM_BYTES);

    init_frame_kernel<<<(SB * FRPIX / 4 + 255) / 256, 256>>>(frames, ts);
    split_W1_kernel<<<dim3(NPXB / 32, H_ / 32), dim3(32, 8)>>>(W1);

    for (int k = 0; k < K_; k++) {
        conv_softmax_kernel<<<SB, 256, convSmem>>>(ck, k);
        gemm1_mma_kernel<<<dim3(2, 8, ZSPLIT), 256, GEMM1_SMEM_BYTES>>>();
        reduce_relu_kernel<<<128, 256>>>(b1);
        gemm2_kernel<<<dim3(4, 8, 4), 256>>>(Wm1, Ws1);
        head_kernel<<<SB, 64>>>(bm1, bs1, Wm2, bm2, Ws2, bs2, eps, out, k);
        if (k < K_ - 1) recon_kernel<<<SB, 256>>>(ck, k);
    }
}